// round 11
// baseline (speedup 1.0000x reference)
#include <cuda_runtime.h>
#include <cuda_bf16.h>
#include <cuda_fp16.h>
#include <math.h>
#include <stdint.h>

#define B_   4
#define C_   256
#define D_   128
#define HW_  16384
#define W_   128
#define T_   16384
#define MAX_DELTA 0.0009765625f   // 0.5/512

__device__ uint8_t g_vm8[(size_t)B_ * HW_ * D_];       // fp8 vm [b][pix][d]
__device__ __half g_feat[(size_t)B_ * T_ * D_];        // fp16 feat [pt][d]
__device__ __nv_bfloat16 g_wp[D_ * C_];                // bf16 Wp [d][c]
__device__ __half g_w1h[D_ * D_];                      // fp16 W1 [j][k]

// ---------------------------------------------------------------------------
__device__ __forceinline__ uint32_t s2u(const void* p) {
    return (uint32_t)__cvta_generic_to_shared(p);
}
__device__ __forceinline__ void cp_async16(void* smem_dst, const void* gmem_src) {
    asm volatile("cp.async.cg.shared.global [%0], [%1], 16;\n"
        :: "r"(s2u(smem_dst)), "l"(gmem_src));
}
__device__ __forceinline__ void ldm_x4(uint32_t r[4], uint32_t addr) {
    asm volatile("ldmatrix.sync.aligned.m8n8.x4.shared.b16 {%0,%1,%2,%3}, [%4];\n"
        : "=r"(r[0]), "=r"(r[1]), "=r"(r[2]), "=r"(r[3]) : "r"(addr));
}
__device__ __forceinline__ void mma_bf16(float c[4], const uint32_t a[4], const uint32_t b[2]) {
    asm volatile("mma.sync.aligned.m16n8k16.row.col.f32.bf16.bf16.f32 "
        "{%0,%1,%2,%3}, {%4,%5,%6,%7}, {%8,%9}, {%0,%1,%2,%3};\n"
        : "+f"(c[0]), "+f"(c[1]), "+f"(c[2]), "+f"(c[3])
        : "r"(a[0]), "r"(a[1]), "r"(a[2]), "r"(a[3]), "r"(b[0]), "r"(b[1]));
}
__device__ __forceinline__ void mma_f16(float c[4], const uint32_t a[4], const uint32_t b[2]) {
    asm volatile("mma.sync.aligned.m16n8k16.row.col.f32.f16.f16.f32 "
        "{%0,%1,%2,%3}, {%4,%5,%6,%7}, {%8,%9}, {%0,%1,%2,%3};\n"
        : "+f"(c[0]), "+f"(c[1]), "+f"(c[2]), "+f"(c[3])
        : "r"(a[0]), "r"(a[1]), "r"(a[2]), "r"(a[3]), "r"(b[0]), "r"(b[1]));
}
__device__ __forceinline__ uint16_t pack_e4m3x2(float lo, float hi) {
    uint16_t r;
    asm("cvt.rn.satfinite.e4m3x2.f32 %0, %1, %2;" : "=h"(r) : "f"(hi), "f"(lo));
    return r;
}
__device__ __forceinline__ __half2 e4m3x2_to_h2(uint32_t u) {
    uint32_t r;
    asm("cvt.rn.f16x2.e4m3x2 %0, %1;" : "=r"(r) : "h"((uint16_t)u));
    return *(__half2*)&r;
}
__device__ __forceinline__ uint32_t pack_bf16x2(float lo, float hi) {
    __nv_bfloat162 p = __floats2bfloat162_rn(lo, hi);
    return *(uint32_t*)&p;
}

// smem layout constants for proj
#define BSTR 264
#define BS_ELEMS  (128 * BSTR)                 // bf16 elems (67584 B)
#define AS32STR 132
#define STAGE_ELEMS (32 * AS32STR)             // fp32 elems per stage (16896 B)
#define PROJ_SMEM (BS_ELEMS * 2 + 2 * STAGE_ELEMS * 4)   // 101376 B

// ---------------------------------------------------------------------------
// Kernel 0: one-time weight conversion.
// ---------------------------------------------------------------------------
__global__ __launch_bounds__(256) void wt_convert(const float* __restrict__ Wp,
                                                  const float* __restrict__ W1)
{
    int i = blockIdx.x * 256 + threadIdx.x;
    if (i < 8192) {
        float4 v = *(const float4*)&Wp[i * 4];
        __nv_bfloat162* dst = (__nv_bfloat162*)&g_wp[i * 4];
        dst[0] = __floats2bfloat162_rn(v.x, v.y);
        dst[1] = __floats2bfloat162_rn(v.z, v.w);
    } else {
        int j = i - 8192;
        float4 v = *(const float4*)&W1[j * 4];
        __half2* dst = (__half2*)&g_w1h[j * 4];
        dst[0] = __floats2half2_rn(v.x, v.y);
        dst[1] = __floats2half2_rn(v.z, v.w);
    }
}

// ---------------------------------------------------------------------------
// Kernel 1: projection GEMM -> fp8 vm.
// fmap streams global->smem fp32 via cp.async (2-stage ring, depth 2);
// A-fragments built directly from fp32 smem (LDS + cvt), no bf16 staging.
// Persistent: 2 m-tiles per block; Wp loaded once per block via cp.async.
// ---------------------------------------------------------------------------
__global__ __launch_bounds__(256, 2) void proj_kernel(const float* __restrict__ fmap)
{
    extern __shared__ __align__(16) char smraw[];
    __nv_bfloat16* Bs = (__nv_bfloat16*)smraw;                    // [128 n][BSTR k]
    float*        As32 = (float*)(smraw + BS_ELEMS * 2);          // [2][32 k][AS32STR m]

    const int b    = blockIdx.y;
    const int tid  = threadIdx.x;
    const int lane = tid & 31, warp = tid >> 5;

    const float* fb = fmap + (size_t)b * C_ * HW_ + blockIdx.x * 256;

    // group 0: whole Wp bf16 -> Bs
    {
        const int row = tid >> 1;
        const int c0  = (tid & 1) * 16;
#pragma unroll
        for (int c = 0; c < 16; c++) {
            int chunk = c0 + c;
            cp_async16(&Bs[row * BSTR + chunk * 8], &g_wp[row * C_ + chunk * 8]);
        }
        asm volatile("cp.async.commit_group;\n" ::: "memory");
    }
    // groups 1,2: fmap chunks 0,1 (chunk g: tile tt=g>>3, kc=g&7; 32k x 128m fp32)
#pragma unroll
    for (int g0 = 0; g0 < 2; g0++) {
        const float* src = fb + (size_t)((g0 & 7) * 32) * HW_ + (g0 >> 3) * 128;
        float* dstS = As32 + (g0 & 1) * STAGE_ELEMS;
#pragma unroll
        for (int i = 0; i < 4; i++) {
            int idx = i * 256 + tid;
            int row = idx >> 5, c = (idx & 31) * 4;
            cp_async16(dstS + row * AS32STR + c, src + (size_t)row * HW_ + c);
        }
        asm volatile("cp.async.commit_group;\n" ::: "memory");
    }

    const int wm = (warp & 3) * 32;
    const int wn = (warp >> 2) * 64;
    const uint32_t bbase = s2u(Bs);

    float acc[2][8][4];
#pragma unroll
    for (int mt = 0; mt < 2; mt++)
#pragma unroll
        for (int nt = 0; nt < 8; nt++)
#pragma unroll
            for (int q = 0; q < 4; q++) acc[mt][nt][q] = 0.f;

    const int mrow0 = lane >> 2;          // fragment row within 16-block
    const int kcol0 = (lane & 3) * 2;     // fragment col pair base

#pragma unroll 1
    for (int g = 0; g < 16; g++) {
        if (g == 15)
            asm volatile("cp.async.wait_group 0;\n" ::: "memory");
        else
            asm volatile("cp.async.wait_group 1;\n" ::: "memory");
        __syncthreads();

        const float* As = As32 + (g & 1) * STAGE_ELEMS;
        const int kc = g & 7;

#pragma unroll
        for (int ks = 0; ks < 2; ks++) {
            const int kb = ks * 16 + kcol0;   // k within chunk for this thread
            uint32_t af[2][4];
#pragma unroll
            for (int mt = 0; mt < 2; mt++) {
                int m0 = wm + mt * 16 + mrow0;
                af[mt][0] = pack_bf16x2(As[kb * AS32STR + m0],
                                        As[(kb + 1) * AS32STR + m0]);
                af[mt][1] = pack_bf16x2(As[kb * AS32STR + m0 + 8],
                                        As[(kb + 1) * AS32STR + m0 + 8]);
                af[mt][2] = pack_bf16x2(As[(kb + 8) * AS32STR + m0],
                                        As[(kb + 9) * AS32STR + m0]);
                af[mt][3] = pack_bf16x2(As[(kb + 8) * AS32STR + m0 + 8],
                                        As[(kb + 9) * AS32STR + m0 + 8]);
            }
            uint32_t bf[8][2];
#pragma unroll
            for (int np = 0; np < 4; np++) {
                int n = wn + np * 16 + (lane & 7) + ((lane >> 4) << 3);
                int k = kc * 32 + ks * 16 + ((lane >> 3) & 1) * 8;
                uint32_t r[4];
                ldm_x4(r, bbase + (n * BSTR + k) * 2);
                bf[2 * np][0]     = r[0];  bf[2 * np][1]     = r[1];
                bf[2 * np + 1][0] = r[2];  bf[2 * np + 1][1] = r[3];
            }
#pragma unroll
            for (int mt = 0; mt < 2; mt++)
#pragma unroll
                for (int nt = 0; nt < 8; nt++)
                    mma_bf16(acc[mt][nt], af[mt], bf[nt]);
        }
        __syncthreads();   // stage (g&1) free for reuse

        if (g + 2 < 16) {
            const int gn = g + 2;
            const float* src = fb + (size_t)((gn & 7) * 32) * HW_ + (gn >> 3) * 128;
            float* dstS = As32 + (gn & 1) * STAGE_ELEMS;
#pragma unroll
            for (int i = 0; i < 4; i++) {
                int idx = i * 256 + tid;
                int row = idx >> 5, c = (idx & 31) * 4;
                cp_async16(dstS + row * AS32STR + c, src + (size_t)row * HW_ + c);
            }
            asm volatile("cp.async.commit_group;\n" ::: "memory");
        }

        if ((g & 7) == 7) {
            // epilogue for tile (g>>3): C frags -> fp8 g_vm8
            uint8_t* outp = g_vm8 +
                ((size_t)b * HW_ + blockIdx.x * 256 + (g >> 3) * 128) * D_;
#pragma unroll
            for (int mt = 0; mt < 2; mt++) {
#pragma unroll
                for (int nt = 0; nt < 8; nt++) {
                    int r0 = wm + mt * 16 + (lane >> 2);
                    int d0 = wn + nt * 8 + (lane & 3) * 2;
                    *(uint16_t*)&outp[(size_t)r0 * D_ + d0] =
                        pack_e4m3x2(acc[mt][nt][0], acc[mt][nt][1]);
                    *(uint16_t*)&outp[(size_t)(r0 + 8) * D_ + d0] =
                        pack_e4m3x2(acc[mt][nt][2], acc[mt][nt][3]);
                    acc[mt][nt][0] = acc[mt][nt][1] = 0.f;
                    acc[mt][nt][2] = acc[mt][nt][3] = 0.f;
                }
            }
        }
    }
}

// ---------------------------------------------------------------------------
// Kernel 2: branch-free 4x4 stencil sampler (R4 shape: warp/point, LDG.32).
// ---------------------------------------------------------------------------
__global__ __launch_bounds__(256, 4) void sample_kernel(const float* __restrict__ coords)
{
    const int tid  = threadIdx.x;
    const int lane = tid & 31, warp = tid >> 5;
    const int ptBase = blockIdx.x * 64 + warp * 8;
    const float inv9 = 1.f / 9.f;

#pragma unroll 1
    for (int i = 0; i < 8; i++) {
        int gpt = ptBase + i;
        int b   = gpt >> 14;

        float cx = coords[2 * gpt], cy = coords[2 * gpt + 1];
        float ix = cx * 127.f, iy = cy * 127.f;
        float xf = floorf(ix), yf = floorf(iy);
        int   x0 = (int)xf,    y0 = (int)yf;
        float fx = ix - xf,    fy = iy - yf;
        float Xw[4] = {1.f - fx, 1.f, 1.f, fx};
        float Yw[4] = {1.f - fy, 1.f, 1.f, fy};

        float wx[4], wy[4];
        int   px[4], py[4];
#pragma unroll
        for (int q = 0; q < 4; q++) {
            int x = x0 - 1 + q;
            bool vx = ((unsigned)x < 128u);
            wx[q] = vx ? Xw[q] : 0.f;
            px[q] = vx ? x : 0;
            int y = y0 - 1 + q;
            bool vy = ((unsigned)y < 128u);
            wy[q] = vy ? (Yw[q] * inv9) : 0.f;
            py[q] = vy ? y : 0;
        }

        const uint32_t* vmb = ((const uint32_t*)g_vm8) + (size_t)b * HW_ * 32 + lane;
        uint32_t off[16];
#pragma unroll
        for (int j = 0; j < 4; j++)
#pragma unroll
            for (int q = 0; q < 4; q++)
                off[j * 4 + q] = (uint32_t)(py[j] * W_ + px[q]) * 32u;

        uint32_t v[16];
#pragma unroll
        for (int t = 0; t < 16; t++) v[t] = vmb[off[t]];

        __half2 a01 = __half2(__float2half(0.f), __float2half(0.f));
        __half2 a23 = a01;
#pragma unroll
        for (int j = 0; j < 4; j++)
#pragma unroll
            for (int q = 0; q < 4; q++) {
                int t = j * 4 + q;
                __half2 w2 = __float2half2_rn(wy[j] * wx[q]);
                a01 = __hfma2(e4m3x2_to_h2(v[t] & 0xffffu), w2, a01);
                a23 = __hfma2(e4m3x2_to_h2(v[t] >> 16), w2, a23);
            }

        uint2 pk;
        pk.x = *(uint32_t*)&a01;
        pk.y = *(uint32_t*)&a23;
        *(uint2*)&g_feat[(size_t)gpt * D_ + lane * 4] = pk;
    }
}

// ---------------------------------------------------------------------------
// Kernel 3: MLP GEMM, 2 tiles per block, 2 CTAs/SM (128-reg cap). (R9 form)
// ---------------------------------------------------------------------------
#define FSTR 136
#define TILE_ELEMS (128 * FSTR)
#define MLP_SMEM ((3 * TILE_ELEMS) * 2 + 2 * 128 * 2 * 4)   // 106496 B
#define NTILES 2

__global__ __launch_bounds__(256, 2) void mlp_kernel(
    const float* __restrict__ coords, const float* __restrict__ b1,
    const float* __restrict__ W2,     const float* __restrict__ b2,
    float* __restrict__ out)
{
    extern __shared__ __align__(16) __half smh[];
    __half* W1h = smh;                             // [128][FSTR]
    __half* Af0 = smh + TILE_ELEMS;
    __half* Af1 = smh + 2 * TILE_ELEMS;
    float*  red = (float*)(smh + 3 * TILE_ELEMS);  // [2][128][2]

    const int tid  = threadIdx.x;
    const int lane = tid & 31, warp = tid >> 5;
    const int wm = (warp & 3) * 32;
    const int wn = (warp >> 2) * 64;
    const size_t tileBase = (size_t)blockIdx.x * NTILES;

    {
#pragma unroll
        for (int i = 0; i < 8; i++) {
            int idx = i * 256 + tid;
            int row = idx >> 4, c8 = (idx & 15) * 8;
            cp_async16(&W1h[row * FSTR + c8], g_w1h + idx * 8);
        }
        const __half* f0 = g_feat + tileBase * 128 * D_;
#pragma unroll
        for (int i = 0; i < 8; i++) {
            int idx = i * 256 + tid;
            int row = idx >> 4, c8 = (idx & 15) * 8;
            cp_async16(&Af0[row * FSTR + c8], f0 + idx * 8);
        }
        asm volatile("cp.async.commit_group;\n" ::: "memory");
        const __half* f1 = f0 + 128 * D_;
#pragma unroll
        for (int i = 0; i < 8; i++) {
            int idx = i * 256 + tid;
            int row = idx >> 4, c8 = (idx & 15) * 8;
            cp_async16(&Af1[row * FSTR + c8], f1 + idx * 8);
        }
        asm volatile("cp.async.commit_group;\n" ::: "memory");
    }

    const uint32_t bbase = s2u(W1h);

#pragma unroll 1
    for (int t = 0; t < NTILES; t++) {
        if (t == 0)
            asm volatile("cp.async.wait_group 1;\n" ::: "memory");
        else
            asm volatile("cp.async.wait_group 0;\n" ::: "memory");
        __syncthreads();

        const int ptBase = (int)(tileBase + t) * 128;
        const uint32_t abase = s2u(t ? Af1 : Af0);

        float acc[2][8][4];
#pragma unroll
        for (int mt = 0; mt < 2; mt++)
#pragma unroll
            for (int nt = 0; nt < 8; nt++)
#pragma unroll
                for (int q = 0; q < 4; q++) acc[mt][nt][q] = 0.f;

#pragma unroll
        for (int kc = 0; kc < 8; kc++) {
            int k0 = kc * 16;
            uint32_t af[2][4];
#pragma unroll
            for (int mt = 0; mt < 2; mt++) {
                int row = wm + mt * 16 + (lane & 15);
                int col = k0 + ((lane >> 4) << 3);
                ldm_x4(af[mt], abase + (row * FSTR + col) * 2);
            }
            uint32_t bf[8][2];
#pragma unroll
            for (int np = 0; np < 4; np++) {
                int n = wn + np * 16 + (lane & 7) + ((lane >> 4) << 3);
                int k = k0 + ((lane >> 3) & 1) * 8;
                uint32_t r[4];
                ldm_x4(r, bbase + (n * FSTR + k) * 2);
                bf[2 * np][0]     = r[0];  bf[2 * np][1]     = r[1];
                bf[2 * np + 1][0] = r[2];  bf[2 * np + 1][1] = r[3];
            }
#pragma unroll
            for (int mt = 0; mt < 2; mt++)
#pragma unroll
                for (int nt = 0; nt < 8; nt++)
                    mma_f16(acc[mt][nt], af[mt], bf[nt]);
        }

        float2 b1v[8], w20v[8], w21v[8];
#pragma unroll
        for (int nt = 0; nt < 8; nt++) {
            int j = wn + nt * 8 + (lane & 3) * 2;
            b1v[nt]  = *(const float2*)&b1[j];
            w20v[nt] = *(const float2*)&W2[j];
            w21v[nt] = *(const float2*)&W2[128 + j];
        }
        float s0[2][2], s1[2][2];
#pragma unroll
        for (int mt = 0; mt < 2; mt++)
#pragma unroll
            for (int hh = 0; hh < 2; hh++) { s0[mt][hh] = 0.f; s1[mt][hh] = 0.f; }
#pragma unroll
        for (int mt = 0; mt < 2; mt++)
#pragma unroll
            for (int nt = 0; nt < 8; nt++) {
                float h00 = fmaxf(acc[mt][nt][0] + b1v[nt].x, 0.f);
                float h01 = fmaxf(acc[mt][nt][1] + b1v[nt].y, 0.f);
                float h10 = fmaxf(acc[mt][nt][2] + b1v[nt].x, 0.f);
                float h11 = fmaxf(acc[mt][nt][3] + b1v[nt].y, 0.f);
                s0[mt][0] = fmaf(w20v[nt].x, h00, s0[mt][0]);
                s0[mt][0] = fmaf(w20v[nt].y, h01, s0[mt][0]);
                s1[mt][0] = fmaf(w21v[nt].x, h00, s1[mt][0]);
                s1[mt][0] = fmaf(w21v[nt].y, h01, s1[mt][0]);
                s0[mt][1] = fmaf(w20v[nt].x, h10, s0[mt][1]);
                s0[mt][1] = fmaf(w20v[nt].y, h11, s0[mt][1]);
                s1[mt][1] = fmaf(w21v[nt].x, h10, s1[mt][1]);
                s1[mt][1] = fmaf(w21v[nt].y, h11, s1[mt][1]);
            }
#pragma unroll
        for (int mt = 0; mt < 2; mt++)
#pragma unroll
            for (int hh = 0; hh < 2; hh++) {
#pragma unroll
                for (int ofs = 1; ofs < 4; ofs <<= 1) {
                    s0[mt][hh] += __shfl_xor_sync(0xffffffffu, s0[mt][hh], ofs);
                    s1[mt][hh] += __shfl_xor_sync(0xffffffffu, s1[mt][hh], ofs);
                }
            }
        if ((lane & 3) == 0) {
            int gg = warp >> 2;
#pragma unroll
            for (int mt = 0; mt < 2; mt++)
#pragma unroll
                for (int hh = 0; hh < 2; hh++) {
                    int row = wm + mt * 16 + (lane >> 2) + 8 * hh;
                    red[(gg * 128 + row) * 2 + 0] = s0[mt][hh];
                    red[(gg * 128 + row) * 2 + 1] = s1[mt][hh];
                }
        }
        __syncthreads();

        {
            int pt = tid >> 1, c = tid & 1;
            float s = b2[c] + red[pt * 2 + c] + red[(128 + pt) * 2 + c];
            float v = tanhf(s) * MAX_DELTA;
            int gi = (ptBase + pt) * 2 + c;
            out[gi] = coords[gi] + v;
        }
        if (t == 0) __syncthreads();
    }
}

// ---------------------------------------------------------------------------
extern "C" void kernel_launch(void* const* d_in, const int* in_sizes, int n_in,
                              void* d_out, int out_size)
{
    (void)in_sizes; (void)n_in; (void)out_size;
    const float* fmap   = (const float*)d_in[0];
    const float* coords = (const float*)d_in[1];
    const float* Wp     = (const float*)d_in[2];
    const float* W1     = (const float*)d_in[3];
    const float* b1     = (const float*)d_in[4];
    const float* W2     = (const float*)d_in[5];
    const float* b2     = (const float*)d_in[6];
    float* out = (float*)d_out;

    wt_convert<<<48, 256>>>(Wp, W1);

    cudaFuncSetAttribute(proj_kernel,
                         cudaFuncAttributeMaxDynamicSharedMemorySize, PROJ_SMEM);
    proj_kernel<<<dim3(HW_ / 256, B_), 256, PROJ_SMEM>>>(fmap);

    sample_kernel<<<(B_ * T_) / 64, 256>>>(coords);

    cudaFuncSetAttribute(mlp_kernel,
                         cudaFuncAttributeMaxDynamicSharedMemorySize, MLP_SMEM);
    mlp_kernel<<<(B_ * T_) / (128 * NTILES), 256, MLP_SMEM>>>(coords, b1, W2, b2, out);
}

// round 12
// speedup vs baseline: 1.0315x; 1.0315x over previous
#include <cuda_runtime.h>
#include <cuda_bf16.h>
#include <cuda_fp16.h>
#include <math.h>
#include <stdint.h>

#define B_   4
#define C_   256
#define D_   128
#define HW_  16384
#define W_   128
#define T_   16384
#define MAX_DELTA 0.0009765625f   // 0.5/512

__device__ uint8_t g_vm8[(size_t)B_ * HW_ * D_];       // fp8 vm [b][pix][d]
__device__ __half g_feat[(size_t)B_ * T_ * D_];        // fp16 feat [pt][d]
__device__ __nv_bfloat16 g_wp[D_ * C_];                // bf16 Wp [d][c]
__device__ __half g_w1h[D_ * D_];                      // fp16 W1 [j][k]

// ---------------------------------------------------------------------------
__device__ __forceinline__ uint32_t s2u(const void* p) {
    return (uint32_t)__cvta_generic_to_shared(p);
}
__device__ __forceinline__ void mbar_init(uint32_t addr, uint32_t cnt) {
    asm volatile("mbarrier.init.shared.b64 [%0], %1;" :: "r"(addr), "r"(cnt) : "memory");
}
__device__ __forceinline__ void mbar_expect_tx(uint32_t addr, uint32_t bytes) {
    asm volatile("mbarrier.arrive.expect_tx.shared.b64 _, [%0], %1;"
        :: "r"(addr), "r"(bytes) : "memory");
}
__device__ __forceinline__ void bulk_g2s(uint32_t dst, const void* src,
                                         uint32_t bytes, uint32_t mbar) {
    asm volatile("cp.async.bulk.shared::cta.global.mbarrier::complete_tx::bytes "
        "[%0], [%1], %2, [%3];"
        :: "r"(dst), "l"(src), "r"(bytes), "r"(mbar) : "memory");
}
__device__ __forceinline__ void mbar_wait(uint32_t mbar, uint32_t parity) {
    uint32_t done;
    do {
        asm volatile("{\n\t.reg .pred p;\n\t"
            "mbarrier.try_wait.parity.acquire.cta.shared::cta.b64 p, [%1], %2;\n\t"
            "selp.b32 %0, 1, 0, p;\n\t}"
            : "=r"(done) : "r"(mbar), "r"(parity) : "memory");
    } while (!done);
}
__device__ __forceinline__ void fence_pa() {
    asm volatile("fence.proxy.async.shared::cta;" ::: "memory");
}
__device__ __forceinline__ void ldm_x4(uint32_t r[4], uint32_t addr) {
    asm volatile("ldmatrix.sync.aligned.m8n8.x4.shared.b16 {%0,%1,%2,%3}, [%4];\n"
        : "=r"(r[0]), "=r"(r[1]), "=r"(r[2]), "=r"(r[3]) : "r"(addr));
}
__device__ __forceinline__ void mma_bf16(float c[4], const uint32_t a[4], const uint32_t b[2]) {
    asm volatile("mma.sync.aligned.m16n8k16.row.col.f32.bf16.bf16.f32 "
        "{%0,%1,%2,%3}, {%4,%5,%6,%7}, {%8,%9}, {%0,%1,%2,%3};\n"
        : "+f"(c[0]), "+f"(c[1]), "+f"(c[2]), "+f"(c[3])
        : "r"(a[0]), "r"(a[1]), "r"(a[2]), "r"(a[3]), "r"(b[0]), "r"(b[1]));
}
__device__ __forceinline__ void mma_f16(float c[4], const uint32_t a[4], const uint32_t b[2]) {
    asm volatile("mma.sync.aligned.m16n8k16.row.col.f32.f16.f16.f32 "
        "{%0,%1,%2,%3}, {%4,%5,%6,%7}, {%8,%9}, {%0,%1,%2,%3};\n"
        : "+f"(c[0]), "+f"(c[1]), "+f"(c[2]), "+f"(c[3])
        : "r"(a[0]), "r"(a[1]), "r"(a[2]), "r"(a[3]), "r"(b[0]), "r"(b[1]));
}
__device__ __forceinline__ uint16_t pack_e4m3x2(float lo, float hi) {
    uint16_t r;
    asm("cvt.rn.satfinite.e4m3x2.f32 %0, %1, %2;" : "=h"(r) : "f"(hi), "f"(lo));
    return r;
}
__device__ __forceinline__ __half2 e4m3x2_to_h2(uint32_t u) {
    uint32_t r;
    asm("cvt.rn.f16x2.e4m3x2 %0, %1;" : "=r"(r) : "h"((uint16_t)u));
    return *(__half2*)&r;
}
__device__ __forceinline__ uint32_t pack_bf16x2(float lo, float hi) {
    __nv_bfloat162 p = __floats2bfloat162_rn(lo, hi);
    return *(uint32_t*)&p;
}

// smem layout constants for proj
#define BSTR 264
#define BS_ELEMS  (128 * BSTR)                 // bf16 elems (67584 B)
#define AS32STR 132
#define STAGE_ELEMS (32 * AS32STR)             // fp32 elems per stage (16896 B)
#define PROJ_BAR_OFF (BS_ELEMS * 2 + 2 * STAGE_ELEMS * 4)   // 101376
#define PROJ_SMEM (PROJ_BAR_OFF + 64)                        // 101440 B

// ---------------------------------------------------------------------------
// Kernel 0: one-time weight conversion.
// ---------------------------------------------------------------------------
__global__ __launch_bounds__(256) void wt_convert(const float* __restrict__ Wp,
                                                  const float* __restrict__ W1)
{
    int i = blockIdx.x * 256 + threadIdx.x;
    if (i < 8192) {
        float4 v = *(const float4*)&Wp[i * 4];
        __nv_bfloat162* dst = (__nv_bfloat162*)&g_wp[i * 4];
        dst[0] = __floats2bfloat162_rn(v.x, v.y);
        dst[1] = __floats2bfloat162_rn(v.z, v.w);
    } else {
        int j = i - 8192;
        float4 v = *(const float4*)&W1[j * 4];
        __half2* dst = (__half2*)&g_w1h[j * 4];
        dst[0] = __floats2half2_rn(v.x, v.y);
        dst[1] = __floats2half2_rn(v.z, v.w);
    }
}

// ---------------------------------------------------------------------------
// Kernel 1: projection GEMM -> fp8 vm.
// All staging via cp.async.bulk (UBLKCP) + mbarrier: Wp = 128x512B rows,
// fmap chunk = 32x512B rows (2-stage ring, depth-2 prefetch).
// Persistent: 2 m-tiles per block.
// ---------------------------------------------------------------------------
__global__ __launch_bounds__(256, 2) void proj_kernel(const float* __restrict__ fmap)
{
    extern __shared__ __align__(16) char smraw[];
    __nv_bfloat16* Bs = (__nv_bfloat16*)smraw;                    // [128 n][BSTR k]
    float*        As32 = (float*)(smraw + BS_ELEMS * 2);          // [2][32 k][AS32STR m]
    const uint32_t barB = s2u(smraw + PROJ_BAR_OFF);  // +0:s0 +8:s1 +16:Wp

    const int b    = blockIdx.y;
    const int tid  = threadIdx.x;
    const int lane = tid & 31, warp = tid >> 5;

    const float* fb = fmap + (size_t)b * C_ * HW_ + blockIdx.x * 256;

    if (tid == 0) {
        mbar_init(barB, 1); mbar_init(barB + 8, 1); mbar_init(barB + 16, 1);
        fence_pa();
    }
    __syncthreads();
    if (tid == 0) {
        mbar_expect_tx(barB + 16, 65536);
        mbar_expect_tx(barB,      16384);
        mbar_expect_tx(barB + 8,  16384);
    }
    __syncthreads();

    if (lane == 0) {
        // Wp rows: warp w -> rows [w*16, w*16+16)
#pragma unroll
        for (int r = 0; r < 16; r++) {
            int row = warp * 16 + r;
            bulk_g2s(s2u(&Bs[row * BSTR]), g_wp + row * C_, 512, barB + 16);
        }
        if (warp == 0) {           // chunk 0: k-rows 0..31, m-off 0
#pragma unroll
            for (int r = 0; r < 32; r++)
                bulk_g2s(s2u(As32 + r * AS32STR), fb + (size_t)r * HW_, 512, barB);
        }
        if (warp == 1) {           // chunk 1: k-rows 32..63, m-off 0
            const float* src = fb + (size_t)32 * HW_;
#pragma unroll
            for (int r = 0; r < 32; r++)
                bulk_g2s(s2u(As32 + STAGE_ELEMS + r * AS32STR),
                         src + (size_t)r * HW_, 512, barB + 8);
        }
    }

    const int wm = (warp & 3) * 32;
    const int wn = (warp >> 2) * 64;
    const uint32_t bbase = s2u(Bs);

    float acc[2][8][4];
#pragma unroll
    for (int mt = 0; mt < 2; mt++)
#pragma unroll
        for (int nt = 0; nt < 8; nt++)
#pragma unroll
            for (int q = 0; q < 4; q++) acc[mt][nt][q] = 0.f;

    const int mrow0 = lane >> 2;
    const int kcol0 = (lane & 3) * 2;

    mbar_wait(barB + 16, 0);   // Wp ready

#pragma unroll 1
    for (int g = 0; g < 16; g++) {
        mbar_wait(barB + (g & 1) * 8, (g >> 1) & 1);

        const float* As = As32 + (g & 1) * STAGE_ELEMS;
        const int kc = g & 7;

#pragma unroll
        for (int ks = 0; ks < 2; ks++) {
            const int kb = ks * 16 + kcol0;
            uint32_t af[2][4];
#pragma unroll
            for (int mt = 0; mt < 2; mt++) {
                int m0 = wm + mt * 16 + mrow0;
                af[mt][0] = pack_bf16x2(As[kb * AS32STR + m0],
                                        As[(kb + 1) * AS32STR + m0]);
                af[mt][1] = pack_bf16x2(As[kb * AS32STR + m0 + 8],
                                        As[(kb + 1) * AS32STR + m0 + 8]);
                af[mt][2] = pack_bf16x2(As[(kb + 8) * AS32STR + m0],
                                        As[(kb + 9) * AS32STR + m0]);
                af[mt][3] = pack_bf16x2(As[(kb + 8) * AS32STR + m0 + 8],
                                        As[(kb + 9) * AS32STR + m0 + 8]);
            }
            uint32_t bf[8][2];
#pragma unroll
            for (int np = 0; np < 4; np++) {
                int n = wn + np * 16 + (lane & 7) + ((lane >> 4) << 3);
                int k = kc * 32 + ks * 16 + ((lane >> 3) & 1) * 8;
                uint32_t r[4];
                ldm_x4(r, bbase + (n * BSTR + k) * 2);
                bf[2 * np][0]     = r[0];  bf[2 * np][1]     = r[1];
                bf[2 * np + 1][0] = r[2];  bf[2 * np + 1][1] = r[3];
            }
#pragma unroll
            for (int mt = 0; mt < 2; mt++)
#pragma unroll
                for (int nt = 0; nt < 8; nt++)
                    mma_bf16(acc[mt][nt], af[mt], bf[nt]);
        }
        __syncthreads();   // all threads done reading stage (g&1)

        if (g + 2 < 16 && tid == 0) {
            const int gn = g + 2;
            const uint32_t bar = barB + (gn & 1) * 8;
            mbar_expect_tx(bar, 16384);
            const float* src = fb + (size_t)((gn & 7) * 32) * HW_ + (gn >> 3) * 128;
            float* dstS = As32 + (gn & 1) * STAGE_ELEMS;
#pragma unroll
            for (int r = 0; r < 32; r++)
                bulk_g2s(s2u(dstS + r * AS32STR), src + (size_t)r * HW_, 512, bar);
        }

        if ((g & 7) == 7) {
            uint8_t* outp = g_vm8 +
                ((size_t)b * HW_ + blockIdx.x * 256 + (g >> 3) * 128) * D_;
#pragma unroll
            for (int mt = 0; mt < 2; mt++) {
#pragma unroll
                for (int nt = 0; nt < 8; nt++) {
                    int r0 = wm + mt * 16 + (lane >> 2);
                    int d0 = wn + nt * 8 + (lane & 3) * 2;
                    *(uint16_t*)&outp[(size_t)r0 * D_ + d0] =
                        pack_e4m3x2(acc[mt][nt][0], acc[mt][nt][1]);
                    *(uint16_t*)&outp[(size_t)(r0 + 8) * D_ + d0] =
                        pack_e4m3x2(acc[mt][nt][2], acc[mt][nt][3]);
                    acc[mt][nt][0] = acc[mt][nt][1] = 0.f;
                    acc[mt][nt][2] = acc[mt][nt][3] = 0.f;
                }
            }
        }
    }
}

// ---------------------------------------------------------------------------
// Kernel 2: branch-free 4x4 stencil sampler (R4 shape: warp/point, LDG.32).
// ---------------------------------------------------------------------------
__global__ __launch_bounds__(256, 4) void sample_kernel(const float* __restrict__ coords)
{
    const int tid  = threadIdx.x;
    const int lane = tid & 31, warp = tid >> 5;
    const int ptBase = blockIdx.x * 64 + warp * 8;
    const float inv9 = 1.f / 9.f;

#pragma unroll 1
    for (int i = 0; i < 8; i++) {
        int gpt = ptBase + i;
        int b   = gpt >> 14;

        float cx = coords[2 * gpt], cy = coords[2 * gpt + 1];
        float ix = cx * 127.f, iy = cy * 127.f;
        float xf = floorf(ix), yf = floorf(iy);
        int   x0 = (int)xf,    y0 = (int)yf;
        float fx = ix - xf,    fy = iy - yf;
        float Xw[4] = {1.f - fx, 1.f, 1.f, fx};
        float Yw[4] = {1.f - fy, 1.f, 1.f, fy};

        float wx[4], wy[4];
        int   px[4], py[4];
#pragma unroll
        for (int q = 0; q < 4; q++) {
            int x = x0 - 1 + q;
            bool vx = ((unsigned)x < 128u);
            wx[q] = vx ? Xw[q] : 0.f;
            px[q] = vx ? x : 0;
            int y = y0 - 1 + q;
            bool vy = ((unsigned)y < 128u);
            wy[q] = vy ? (Yw[q] * inv9) : 0.f;
            py[q] = vy ? y : 0;
        }

        const uint32_t* vmb = ((const uint32_t*)g_vm8) + (size_t)b * HW_ * 32 + lane;
        uint32_t off[16];
#pragma unroll
        for (int j = 0; j < 4; j++)
#pragma unroll
            for (int q = 0; q < 4; q++)
                off[j * 4 + q] = (uint32_t)(py[j] * W_ + px[q]) * 32u;

        uint32_t v[16];
#pragma unroll
        for (int t = 0; t < 16; t++) v[t] = vmb[off[t]];

        __half2 a01 = __half2(__float2half(0.f), __float2half(0.f));
        __half2 a23 = a01;
#pragma unroll
        for (int j = 0; j < 4; j++)
#pragma unroll
            for (int q = 0; q < 4; q++) {
                int t = j * 4 + q;
                __half2 w2 = __float2half2_rn(wy[j] * wx[q]);
                a01 = __hfma2(e4m3x2_to_h2(v[t] & 0xffffu), w2, a01);
                a23 = __hfma2(e4m3x2_to_h2(v[t] >> 16), w2, a23);
            }

        uint2 pk;
        pk.x = *(uint32_t*)&a01;
        pk.y = *(uint32_t*)&a23;
        *(uint2*)&g_feat[(size_t)gpt * D_ + lane * 4] = pk;
    }
}

// ---------------------------------------------------------------------------
// Kernel 3: MLP GEMM, 2 tiles per block, 2 CTAs/SM (128-reg cap).
// Prologue via cp.async.bulk rows + 3 mbarriers (W1 / feat0 / feat1).
// ---------------------------------------------------------------------------
#define FSTR 136
#define TILE_ELEMS (128 * FSTR)
#define MLP_BAR_OFF ((3 * TILE_ELEMS) * 2 + 2 * 128 * 2 * 4)   // 106496
#define MLP_SMEM (MLP_BAR_OFF + 64)                            // 106560 B
#define NTILES 2

__global__ __launch_bounds__(256, 2) void mlp_kernel(
    const float* __restrict__ coords, const float* __restrict__ b1,
    const float* __restrict__ W2,     const float* __restrict__ b2,
    float* __restrict__ out)
{
    extern __shared__ __align__(16) __half smh[];
    __half* W1h = smh;                             // [128][FSTR]
    __half* Af0 = smh + TILE_ELEMS;
    __half* Af1 = smh + 2 * TILE_ELEMS;
    float*  red = (float*)(smh + 3 * TILE_ELEMS);  // [2][128][2]
    const uint32_t barB = s2u((char*)smh + MLP_BAR_OFF);  // +0:W1 +8:f0 +16:f1

    const int tid  = threadIdx.x;
    const int lane = tid & 31, warp = tid >> 5;
    const int wm = (warp & 3) * 32;
    const int wn = (warp >> 2) * 64;
    const size_t tileBase = (size_t)blockIdx.x * NTILES;

    if (tid == 0) {
        mbar_init(barB, 1); mbar_init(barB + 8, 1); mbar_init(barB + 16, 1);
        fence_pa();
    }
    __syncthreads();
    if (tid == 0) {
        mbar_expect_tx(barB,      32768);
        mbar_expect_tx(barB + 8,  32768);
        mbar_expect_tx(barB + 16, 32768);
    }
    __syncthreads();

    if (lane == 0) {
        const __half* f0 = g_feat + tileBase * 128 * D_;
        const __half* f1 = f0 + 128 * D_;
#pragma unroll
        for (int r = 0; r < 16; r++) {
            int row = warp * 16 + r;
            bulk_g2s(s2u(&W1h[row * FSTR]), g_w1h + row * 128, 256, barB);
            bulk_g2s(s2u(&Af0[row * FSTR]), f0 + row * 128, 256, barB + 8);
            bulk_g2s(s2u(&Af1[row * FSTR]), f1 + row * 128, 256, barB + 16);
        }
    }

    const uint32_t bbase = s2u(W1h);

#pragma unroll 1
    for (int t = 0; t < NTILES; t++) {
        if (t == 0) { mbar_wait(barB, 0); mbar_wait(barB + 8, 0); }
        else        { mbar_wait(barB + 16, 0); }

        const int ptBase = (int)(tileBase + t) * 128;
        const uint32_t abase = s2u(t ? Af1 : Af0);

        float acc[2][8][4];
#pragma unroll
        for (int mt = 0; mt < 2; mt++)
#pragma unroll
            for (int nt = 0; nt < 8; nt++)
#pragma unroll
                for (int q = 0; q < 4; q++) acc[mt][nt][q] = 0.f;

#pragma unroll
        for (int kc = 0; kc < 8; kc++) {
            int k0 = kc * 16;
            uint32_t af[2][4];
#pragma unroll
            for (int mt = 0; mt < 2; mt++) {
                int row = wm + mt * 16 + (lane & 15);
                int col = k0 + ((lane >> 4) << 3);
                ldm_x4(af[mt], abase + (row * FSTR + col) * 2);
            }
            uint32_t bf[8][2];
#pragma unroll
            for (int np = 0; np < 4; np++) {
                int n = wn + np * 16 + (lane & 7) + ((lane >> 4) << 3);
                int k = k0 + ((lane >> 3) & 1) * 8;
                uint32_t r[4];
                ldm_x4(r, bbase + (n * FSTR + k) * 2);
                bf[2 * np][0]     = r[0];  bf[2 * np][1]     = r[1];
                bf[2 * np + 1][0] = r[2];  bf[2 * np + 1][1] = r[3];
            }
#pragma unroll
            for (int mt = 0; mt < 2; mt++)
#pragma unroll
                for (int nt = 0; nt < 8; nt++)
                    mma_f16(acc[mt][nt], af[mt], bf[nt]);
        }

        float2 b1v[8], w20v[8], w21v[8];
#pragma unroll
        for (int nt = 0; nt < 8; nt++) {
            int j = wn + nt * 8 + (lane & 3) * 2;
            b1v[nt]  = *(const float2*)&b1[j];
            w20v[nt] = *(const float2*)&W2[j];
            w21v[nt] = *(const float2*)&W2[128 + j];
        }
        float s0[2][2], s1[2][2];
#pragma unroll
        for (int mt = 0; mt < 2; mt++)
#pragma unroll
            for (int hh = 0; hh < 2; hh++) { s0[mt][hh] = 0.f; s1[mt][hh] = 0.f; }
#pragma unroll
        for (int mt = 0; mt < 2; mt++)
#pragma unroll
            for (int nt = 0; nt < 8; nt++) {
                float h00 = fmaxf(acc[mt][nt][0] + b1v[nt].x, 0.f);
                float h01 = fmaxf(acc[mt][nt][1] + b1v[nt].y, 0.f);
                float h10 = fmaxf(acc[mt][nt][2] + b1v[nt].x, 0.f);
                float h11 = fmaxf(acc[mt][nt][3] + b1v[nt].y, 0.f);
                s0[mt][0] = fmaf(w20v[nt].x, h00, s0[mt][0]);
                s0[mt][0] = fmaf(w20v[nt].y, h01, s0[mt][0]);
                s1[mt][0] = fmaf(w21v[nt].x, h00, s1[mt][0]);
                s1[mt][0] = fmaf(w21v[nt].y, h01, s1[mt][0]);
                s0[mt][1] = fmaf(w20v[nt].x, h10, s0[mt][1]);
                s0[mt][1] = fmaf(w20v[nt].y, h11, s0[mt][1]);
                s1[mt][1] = fmaf(w21v[nt].x, h10, s1[mt][1]);
                s1[mt][1] = fmaf(w21v[nt].y, h11, s1[mt][1]);
            }
#pragma unroll
        for (int mt = 0; mt < 2; mt++)
#pragma unroll
            for (int hh = 0; hh < 2; hh++) {
#pragma unroll
                for (int ofs = 1; ofs < 4; ofs <<= 1) {
                    s0[mt][hh] += __shfl_xor_sync(0xffffffffu, s0[mt][hh], ofs);
                    s1[mt][hh] += __shfl_xor_sync(0xffffffffu, s1[mt][hh], ofs);
                }
            }
        if ((lane & 3) == 0) {
            int gg = warp >> 2;
#pragma unroll
            for (int mt = 0; mt < 2; mt++)
#pragma unroll
                for (int hh = 0; hh < 2; hh++) {
                    int row = wm + mt * 16 + (lane >> 2) + 8 * hh;
                    red[(gg * 128 + row) * 2 + 0] = s0[mt][hh];
                    red[(gg * 128 + row) * 2 + 1] = s1[mt][hh];
                }
        }
        __syncthreads();

        {
            int pt = tid >> 1, c = tid & 1;
            float s = b2[c] + red[pt * 2 + c] + red[(128 + pt) * 2 + c];
            float v = tanhf(s) * MAX_DELTA;
            int gi = (ptBase + pt) * 2 + c;
            out[gi] = coords[gi] + v;
        }
        if (t == 0) __syncthreads();
    }
}

// ---------------------------------------------------------------------------
extern "C" void kernel_launch(void* const* d_in, const int* in_sizes, int n_in,
                              void* d_out, int out_size)
{
    (void)in_sizes; (void)n_in; (void)out_size;
    const float* fmap   = (const float*)d_in[0];
    const float* coords = (const float*)d_in[1];
    const float* Wp     = (const float*)d_in[2];
    const float* W1     = (const float*)d_in[3];
    const float* b1     = (const float*)d_in[4];
    const float* W2     = (const float*)d_in[5];
    const float* b2     = (const float*)d_in[6];
    float* out = (float*)d_out;

    wt_convert<<<48, 256>>>(Wp, W1);

    cudaFuncSetAttribute(proj_kernel,
                         cudaFuncAttributeMaxDynamicSharedMemorySize, PROJ_SMEM);
    proj_kernel<<<dim3(HW_ / 256, B_), 256, PROJ_SMEM>>>(fmap);

    sample_kernel<<<(B_ * T_) / 64, 256>>>(coords);

    cudaFuncSetAttribute(mlp_kernel,
                         cudaFuncAttributeMaxDynamicSharedMemorySize, MLP_SMEM);
    mlp_kernel<<<(B_ * T_) / (128 * NTILES), 256, MLP_SMEM>>>(coords, b1, W2, b2, out);
}